// round 13
// baseline (speedup 1.0000x reference)
#include <cuda_runtime.h>
#include <cuda_fp16.h>
#include <math.h>
#include <stdint.h>

#define SLEN 2048
#define BATCH 4
#define DMODEL 1024
#define NHEAD 16
#define HDIM 64
#define FFDIM 4096
#define NROW (SLEN*BATCH)      /* 8192 */
#define LDAQ (BATCH*DMODEL)    /* 4096 */

// ------------------------- static scratch -----------------------------------
__device__ __half g_state_h[NROW*DMODEL];
__device__ __half g_wq_h[DMODEL*DMODEL];
__device__ __half g_wk_h[DMODEL*DMODEL];
__device__ __half g_wv_h[DMODEL*DMODEL];
__device__ __half g_wo_h[DMODEL*DMODEL];
__device__ __half g_w1_h[FFDIM*DMODEL];
__device__ __half g_w2_h[DMODEL*FFDIM];
__device__ __half g_qh [NROW*DMODEL];
__device__ __half g_kh [NROW*DMODEL];
__device__ __half g_vh [NROW*DMODEL];
__device__ __half g_att_h[NROW*DMODEL];
__device__ __half g_x1_h[NROW*DMODEL];
__device__ __half g_hh [NROW*FFDIM];
__device__ float  g_y  [NROW*DMODEL];
__device__ float  g_x1 [NROW*DMODEL];
__device__ float  g_y2 [NROW*DMODEL];

// --------------------------- helpers ----------------------------------------
__device__ __forceinline__ unsigned pk2h(float x, float y) {
    __half2 h = __floats2half2_rn(x, y);
    return *(unsigned*)&h;
}
__device__ __forceinline__ void mma16(float* c, const unsigned* a, unsigned b0, unsigned b1) {
    asm("mma.sync.aligned.m16n8k16.row.col.f32.f16.f16.f32 "
        "{%0,%1,%2,%3},{%4,%5,%6,%7},{%8,%9},{%0,%1,%2,%3};"
        : "+f"(c[0]), "+f"(c[1]), "+f"(c[2]), "+f"(c[3])
        : "r"(a[0]), "r"(a[1]), "r"(a[2]), "r"(a[3]), "r"(b0), "r"(b1));
}
__device__ __forceinline__ void cp16(unsigned dst, const void* src) {
    asm volatile("cp.async.ca.shared.global [%0], [%1], 16;" :: "r"(dst), "l"(src));
}
__device__ __forceinline__ void ldm4(unsigned& r0, unsigned& r1, unsigned& r2, unsigned& r3,
                                     unsigned addr) {
    asm volatile("ldmatrix.sync.aligned.m8n8.x4.shared.b16 {%0,%1,%2,%3}, [%4];"
                 : "=r"(r0), "=r"(r1), "=r"(r2), "=r"(r3) : "r"(addr));
}
__device__ __forceinline__ void ldm4t(unsigned& r0, unsigned& r1, unsigned& r2, unsigned& r3,
                                      unsigned addr) {
    asm volatile("ldmatrix.sync.aligned.m8n8.x4.trans.shared.b16 {%0,%1,%2,%3}, [%4];"
                 : "=r"(r0), "=r"(r1), "=r"(r2), "=r"(r3) : "r"(addr));
}

// single-launch fp32 -> fp16 convert of all 7 tensors (grid.z selects segment)
__global__ void f2h_all(const float* s,  __half* so,
                        const float* w0, __half* o0, const float* w1, __half* o1,
                        const float* w2, __half* o2, const float* w3, __half* o3,
                        const float* w4, __half* o4, const float* w5, __half* o5)
{
    const int z = blockIdx.z;
    const float* in; __half* out; int n8;
    switch (z) {
        case 0: in = s;  out = so; n8 = NROW*DMODEL/8;   break;
        case 1: in = w0; out = o0; n8 = DMODEL*DMODEL/8; break;
        case 2: in = w1; out = o1; n8 = DMODEL*DMODEL/8; break;
        case 3: in = w2; out = o2; n8 = DMODEL*DMODEL/8; break;
        case 4: in = w3; out = o3; n8 = DMODEL*DMODEL/8; break;
        case 5: in = w4; out = o4; n8 = FFDIM*DMODEL/8;  break;
        default:in = w5; out = o5; n8 = DMODEL*FFDIM/8;  break;
    }
    int i = blockIdx.x * blockDim.x + threadIdx.x;
    if (i < n8) {
        const float4* p = (const float4*)in + 2*i;
        float4 a = p[0], b = p[1];
        uint4 o = make_uint4(pk2h(a.x,a.y), pk2h(a.z,a.w), pk2h(b.x,b.y), pk2h(b.z,b.w));
        ((uint4*)out)[i] = o;
    }
}

// ---------------------------------------------------------------------------
// fp16 dense GEMM:  C[M,N] = (A[M,K] * W[N,K]^T + bias) * oscale  (opt ReLU)
// 256x128xBK32 block, 4-stage cp.async (120KB dyn smem), 8 warps of 64x64,
// m16n8k16 + ldmatrix.  OM: 0 = fp32 out, 1 = fp16 out, 2 = fp16 out + ReLU
// ---------------------------------------------------------------------------
#define GPITCH 40                        /* f16 per smem row */
#define ASLOTB (256*GPITCH*2)            /* 20480 B per A stage */
#define BSLOTB (128*GPITCH*2)            /* 10240 B per B stage */
#define G_SMEM (4*(ASLOTB+BSLOTB))       /* 122880 */

template<int OM>
__device__ __forceinline__
void gemm_h_body(const __half* __restrict__ A, const __half* __restrict__ W,
                 const float* __restrict__ bias, void* __restrict__ Cout,
                 int N, int K, float oscale, void* gsm, int bm, int bn)
{
    const int tid = threadIdx.x;
    const int lane = tid & 31, wid = tid >> 5;
    const int wm = wid >> 1, wn = wid & 1;        // 4 x 2 warp grid, 64x64 tiles
    const int grp = lane >> 2, qd = lane & 3;
    const int row_in = lane & 7, mat = lane >> 3;

    const unsigned sa = (unsigned)__cvta_generic_to_shared(gsm);
    const unsigned sb = sa + 4*ASLOTB;

    // A load: one full 32-half row per thread (4 cp16)
    const __half* Ar = A + (size_t)(bm + tid) * K;
    const unsigned dA = sa + (unsigned)(tid*GPITCH*2);
    // B load: half row per thread (2 cp16)
    const int rb = tid >> 1, sgb = (tid & 1) * 16;
    const __half* Wr = W + (size_t)(bn + rb) * K + sgb;
    const unsigned dB = sb + (unsigned)((rb*GPITCH + sgb)*2);

    const unsigned a_base = (unsigned)(((wm*64 + (mat&1)*8 + row_in)*GPITCH + (mat>>1)*8)*2);
    const unsigned b_base = (unsigned)(((wn*64 + (mat>>1)*8 + row_in)*GPITCH + (mat&1)*8)*2);

    const int ktot = K >> 5;

    float acc[4][8][4];
#pragma unroll
    for (int i = 0; i < 4; i++)
#pragma unroll
        for (int j = 0; j < 8; j++)
#pragma unroll
            for (int x = 0; x < 4; x++) acc[i][j][x] = 0.f;

#pragma unroll
    for (int p = 0; p < 3; p++) {
        const unsigned oa = p * ASLOTB, ob = p * BSLOTB;
        cp16(dA + oa,      Ar + p*32);
        cp16(dA + oa + 16, Ar + p*32 + 8);
        cp16(dA + oa + 32, Ar + p*32 + 16);
        cp16(dA + oa + 48, Ar + p*32 + 24);
        cp16(dB + ob,      Wr + p*32);
        cp16(dB + ob + 16, Wr + p*32 + 8);
        asm volatile("cp.async.commit_group;" ::: "memory");
    }

    for (int kt = 0; kt < ktot; kt++) {
        asm volatile("cp.async.wait_group 2;" ::: "memory");
        __syncthreads();
        const int nk = kt + 3;
        if (nk < ktot) {
            const unsigned oa = (nk & 3) * ASLOTB, ob = (nk & 3) * BSLOTB;
            cp16(dA + oa,      Ar + nk*32);
            cp16(dA + oa + 16, Ar + nk*32 + 8);
            cp16(dA + oa + 32, Ar + nk*32 + 16);
            cp16(dA + oa + 48, Ar + nk*32 + 24);
            cp16(dB + ob,      Wr + nk*32);
            cp16(dB + ob + 16, Wr + nk*32 + 8);
        }
        asm volatile("cp.async.commit_group;" ::: "memory");

        const unsigned slA = sa + (kt & 3) * ASLOTB;
        const unsigned slB = sb + (kt & 3) * BSLOTB;
#pragma unroll
        for (int kk = 0; kk < 32; kk += 16) {
            unsigned a[4][4], b[8][2];
#pragma unroll
            for (int mi = 0; mi < 4; mi++)
                ldm4(a[mi][0], a[mi][1], a[mi][2], a[mi][3],
                     slA + a_base + (unsigned)(mi*16*GPITCH*2 + kk*2));
#pragma unroll
            for (int g = 0; g < 4; g++) {
                unsigned q0, q1, q2, q3;
                ldm4(q0, q1, q2, q3,
                     slB + b_base + (unsigned)(g*16*GPITCH*2 + kk*2));
                b[2*g][0] = q0; b[2*g][1] = q1;
                b[2*g+1][0] = q2; b[2*g+1][1] = q3;
            }
#pragma unroll
            for (int mi = 0; mi < 4; mi++)
#pragma unroll
                for (int ni = 0; ni < 8; ni++)
                    mma16(acc[mi][ni], a[mi], b[ni][0], b[ni][1]);
        }
    }

#pragma unroll
    for (int mi = 0; mi < 4; mi++) {
        const int row = bm + wm*64 + mi*16 + grp;
#pragma unroll
        for (int ni = 0; ni < 8; ni++) {
            const int col = bn + wn*64 + ni*8 + qd*2;
            float g0 = bias[col], g1 = bias[col+1];
            float o0 = (acc[mi][ni][0] + g0) * oscale;
            float o1 = (acc[mi][ni][1] + g1) * oscale;
            float o2 = (acc[mi][ni][2] + g0) * oscale;
            float o3 = (acc[mi][ni][3] + g1) * oscale;
            if (OM == 2) { o0=fmaxf(o0,0.f); o1=fmaxf(o1,0.f); o2=fmaxf(o2,0.f); o3=fmaxf(o3,0.f); }
            if (OM == 0) {
                float* Cf = (float*)Cout;
                *(float2*)(Cf + (size_t)row    * N + col) = make_float2(o0, o1);
                *(float2*)(Cf + (size_t)(row+8)* N + col) = make_float2(o2, o3);
            } else {
                __half* Ch = (__half*)Cout;
                *(unsigned*)(Ch + (size_t)row    * N + col) = pk2h(o0, o1);
                *(unsigned*)(Ch + (size_t)(row+8)* N + col) = pk2h(o2, o3);
            }
        }
    }
}

template<int OM>
__global__ __launch_bounds__(256, 1)
void gemm_h(const __half* __restrict__ A, const __half* __restrict__ W,
            const float* __restrict__ bias, void* __restrict__ Cout, int N, int K)
{
    extern __shared__ char gsm[];
    gemm_h_body<OM>(A, W, bias, Cout, N, K, 1.f, gsm, blockIdx.y*256, blockIdx.x*128);
}

// fused QKV: blockIdx.z selects weight/bias/output; q gets 0.125 scale
__global__ __launch_bounds__(256, 1)
void gemm_qkv_h(const __half* __restrict__ A,
                const __half* __restrict__ Wq, const __half* __restrict__ Wk,
                const __half* __restrict__ Wv,
                const float* __restrict__ bq, const float* __restrict__ bk,
                const float* __restrict__ bv,
                __half* __restrict__ Cq, __half* __restrict__ Ck, __half* __restrict__ Cv)
{
    extern __shared__ char gsm2[];
    const int z = blockIdx.z;
    const __half* W = (z == 0) ? Wq : (z == 1) ? Wk : Wv;
    const float* bias = (z == 0) ? bq : (z == 1) ? bk : bv;
    __half* C         = (z == 0) ? Cq : (z == 1) ? Ck : Cv;
    const float sc    = (z == 0) ? 0.125f : 1.f;
    gemm_h_body<1>(A, W, bias, C, DMODEL, DMODEL, sc, gsm2, blockIdx.y*256, blockIdx.x*128);
}

// ---------------------------------------------------------------------------
// Fused flash attention, fp16, m16n8k16, double-buffered K/V via cp.async.
// Q pre-scaled by 1/8 at QKV epilogue. Output fp16 [s*B+b, h*64+d].
// ---------------------------------------------------------------------------
#define KVSTAGE_B (64*72*2)     /* bytes per K (or V) stage */
#define FLASH_SMEM ((128*72 + 2*64*72 + 2*64*72 + 128*72)*2 + 256*4*2 + 2048)

__global__ __launch_bounds__(256, 2)
void flash_attn_h(const __half* __restrict__ Q, const __half* __restrict__ K,
                  const __half* __restrict__ V, const void* __restrict__ mask,
                  __half* __restrict__ O)
{
    extern __shared__ __half sm_h[];
    __half* Qs = sm_h;                  // 128*72
    __half* Ks = Qs + 128*72;           // 2 stages x 64*72
    __half* Vs = Ks + 2*64*72;          // 2 stages x 64*72
    __half* Ps = Vs + 2*64*72;          // 128*72
    float* redm = (float*)(Ps + 128*72);  // 256
    float* redl = redm + 256;             // 256
    unsigned char* msk = (unsigned char*)(redl + 256);  // 2048
    __shared__ int s_end;

    const int tid = threadIdx.x, lane = tid & 31, wid = tid >> 5;
    const int wm = wid >> 1, wn = wid & 1;       // 4 x 2 warps, 32x32 tiles
    const int grp = lane >> 2, qd = lane & 3;
    const int row_in = lane & 7, mat = lane >> 3;
    const int bh = blockIdx.y, b = bh >> 4, h = bh & 15;
    const int bm = blockIdx.x * 128;

    const __half* qb = Q + b*DMODEL + h*HDIM;
    const __half* kb = K + b*DMODEL + h*HDIM;
    const __half* vb = V + b*DMODEL + h*HDIM;

    const unsigned sQ = (unsigned)__cvta_generic_to_shared(Qs);
    const unsigned sK = (unsigned)__cvta_generic_to_shared(Ks);
    const unsigned sV = (unsigned)__cvta_generic_to_shared(Vs);
    const unsigned sP = (unsigned)__cvta_generic_to_shared(Ps);

    const unsigned aqb = (unsigned)(((wm*32 + (mat&1)*8 + row_in)*72 + (mat>>1)*8)*2);
    const unsigned bkb = (unsigned)(((wn*32 + (mat>>1)*8 + row_in)*72 + (mat&1)*8)*2);
    const unsigned vtb = (unsigned)((((mat&1)*8 + row_in)*72 + wn*32 + (mat>>1)*8)*2);

    const int rkv = tid >> 2, skv = (tid & 3) * 16;

    if (tid == 0) s_end = SLEN;
    // Q tile -> smem (group 1)
    {
        const int r = tid >> 1, sg = (tid & 1) * 32;
        const __half* src = qb + (size_t)(bm + r) * LDAQ + sg;
        const unsigned dst = sQ + (unsigned)((r*72 + sg)*2);
        cp16(dst,      src);
        cp16(dst + 16, src + 8);
        cp16(dst + 32, src + 16);
        cp16(dst + 48, src + 24);
        asm volatile("cp.async.commit_group;" ::: "memory");
    }
    // KV tile 0 -> stage 0 (group 2)
    {
        const __half* ks = kb + (size_t)rkv * LDAQ + skv;
        const __half* vs = vb + (size_t)rkv * LDAQ + skv;
        const unsigned dk = sK + (unsigned)((rkv*72 + skv)*2);
        const unsigned dv = sV + (unsigned)((rkv*72 + skv)*2);
        cp16(dk,      ks); cp16(dk + 16, ks + 8);
        cp16(dv,      vs); cp16(dv + 16, vs + 8);
        asm volatile("cp.async.commit_group;" ::: "memory");
    }
    // mask row -> smem (u8-bool or int32 probed at runtime)
    {
        const unsigned char* m8  = (const unsigned char*)mask;
        const int*           m32 = (const int*)mask;
        const bool isu8 = (m8[SLEN - 1] == 1);
        for (int t = tid; t < SLEN; t += 256)
            msk[t] = isu8 ? (m8[(size_t)b*SLEN + t] != 0)
                          : (m32[(size_t)b*SLEN + t] != 0);
    }
    asm volatile("cp.async.wait_group 0;" ::: "memory");
    __syncthreads();
    {
        int lm = SLEN;
        for (int t = tid; t < SLEN; t += 256)
            if (msk[t]) { lm = t; break; }
        if (lm < SLEN) atomicMin(&s_end, lm);
    }
    __syncthreads();
    const int kv_end = min(SLEN, (s_end + 63) & ~63);

    float m_st[2][2], l_st[2][2];
    float oacc[2][4][4];
#pragma unroll
    for (int mi = 0; mi < 2; mi++) {
        m_st[mi][0] = -INFINITY; m_st[mi][1] = -INFINITY;
        l_st[mi][0] = 0.f;       l_st[mi][1] = 0.f;
#pragma unroll
        for (int ni = 0; ni < 4; ni++)
#pragma unroll
            for (int x = 0; x < 4; x++) oacc[mi][ni][x] = 0.f;
    }

    for (int kt = 0; kt < kv_end; kt += 64) {
        const int st = (kt >> 6) & 1;
        __syncthreads();
        if (kt + 64 < kv_end) {
            const __half* ks = kb + (size_t)(kt + 64 + rkv) * LDAQ + skv;
            const __half* vs = vb + (size_t)(kt + 64 + rkv) * LDAQ + skv;
            const unsigned dk = sK + (unsigned)((st^1)*KVSTAGE_B) + (unsigned)((rkv*72 + skv)*2);
            const unsigned dv = sV + (unsigned)((st^1)*KVSTAGE_B) + (unsigned)((rkv*72 + skv)*2);
            cp16(dk,      ks); cp16(dk + 16, ks + 8);
            cp16(dv,      vs); cp16(dv + 16, vs + 8);
        }
        asm volatile("cp.async.commit_group;" ::: "memory");
        asm volatile("cp.async.wait_group 1;" ::: "memory");
        __syncthreads();

        const unsigned sKst = sK + (unsigned)(st*KVSTAGE_B);
        const unsigned sVst = sV + (unsigned)(st*KVSTAGE_B);

        // S = Q * K^T
        float sacc[2][4][4];
#pragma unroll
        for (int mi = 0; mi < 2; mi++)
#pragma unroll
            for (int ni = 0; ni < 4; ni++)
#pragma unroll
                for (int x = 0; x < 4; x++) sacc[mi][ni][x] = 0.f;
#pragma unroll
        for (int kk = 0; kk < 64; kk += 16) {
            unsigned a[2][4], bb[4][2];
#pragma unroll
            for (int mi = 0; mi < 2; mi++)
                ldm4(a[mi][0], a[mi][1], a[mi][2], a[mi][3],
                     sQ + aqb + (unsigned)(mi*16*72*2 + kk*2));
#pragma unroll
            for (int h2 = 0; h2 < 2; h2++) {
                unsigned q0, q1, q2, q3;
                ldm4(q0, q1, q2, q3, sKst + bkb + (unsigned)(h2*16*72*2 + kk*2));
                bb[2*h2][0] = q0; bb[2*h2][1] = q1;
                bb[2*h2+1][0] = q2; bb[2*h2+1][1] = q3;
            }
#pragma unroll
            for (int mi = 0; mi < 2; mi++)
#pragma unroll
                for (int ni = 0; ni < 4; ni++)
                    mma16(sacc[mi][ni], a[mi], bb[ni][0], bb[ni][1]);
        }
        // mask
#pragma unroll
        for (int ni = 0; ni < 4; ni++) {
            const int c0 = kt + wn*32 + ni*8 + qd*2;
            if (msk[c0]) {
                sacc[0][ni][0] = -INFINITY; sacc[0][ni][2] = -INFINITY;
                sacc[1][ni][0] = -INFINITY; sacc[1][ni][2] = -INFINITY;
            }
            if (msk[c0+1]) {
                sacc[0][ni][1] = -INFINITY; sacc[0][ni][3] = -INFINITY;
                sacc[1][ni][1] = -INFINITY; sacc[1][ni][3] = -INFINITY;
            }
        }
        // row max
#pragma unroll
        for (int mi = 0; mi < 2; mi++)
#pragma unroll
            for (int hf = 0; hf < 2; hf++) {
                float mx = -INFINITY;
#pragma unroll
                for (int ni = 0; ni < 4; ni++)
                    mx = fmaxf(mx, fmaxf(sacc[mi][ni][hf*2], sacc[mi][ni][hf*2+1]));
                mx = fmaxf(mx, __shfl_xor_sync(0xffffffffu, mx, 1));
                mx = fmaxf(mx, __shfl_xor_sync(0xffffffffu, mx, 2));
                if (qd == 0) redm[wn*128 + wm*32 + mi*16 + hf*8 + grp] = mx;
            }
        __syncthreads();

        float sc[2][2];
#pragma unroll
        for (int mi = 0; mi < 2; mi++)
#pragma unroll
            for (int hf = 0; hf < 2; hf++) {
                const int row = wm*32 + mi*16 + hf*8 + grp;
                const float tm = fmaxf(redm[row], redm[128 + row]);
                const float mnew = fmaxf(m_st[mi][hf], tm);
                sc[mi][hf] = __expf(m_st[mi][hf] - mnew);
                m_st[mi][hf] = mnew;
            }
        float ls[2][2] = {{0.f,0.f},{0.f,0.f}};
#pragma unroll
        for (int mi = 0; mi < 2; mi++) {
            const int r = wm*32 + mi*16 + grp;
#pragma unroll
            for (int ni = 0; ni < 4; ni++) {
                const int c = wn*32 + ni*8 + qd*2;
                float p0 = __expf(sacc[mi][ni][0] - m_st[mi][0]);
                float p1 = __expf(sacc[mi][ni][1] - m_st[mi][0]);
                float p2 = __expf(sacc[mi][ni][2] - m_st[mi][1]);
                float p3 = __expf(sacc[mi][ni][3] - m_st[mi][1]);
                ls[mi][0] += p0 + p1;
                ls[mi][1] += p2 + p3;
                *(unsigned*)(Ps + r*72 + c)     = pk2h(p0, p1);
                *(unsigned*)(Ps + (r+8)*72 + c) = pk2h(p2, p3);
            }
        }
#pragma unroll
        for (int mi = 0; mi < 2; mi++)
#pragma unroll
            for (int hf = 0; hf < 2; hf++) {
                float s = ls[mi][hf];
                s += __shfl_xor_sync(0xffffffffu, s, 1);
                s += __shfl_xor_sync(0xffffffffu, s, 2);
                if (qd == 0) redl[wn*128 + wm*32 + mi*16 + hf*8 + grp] = s;
            }
        __syncthreads();
#pragma unroll
        for (int mi = 0; mi < 2; mi++)
#pragma unroll
            for (int hf = 0; hf < 2; hf++) {
                const int row = wm*32 + mi*16 + hf*8 + grp;
                l_st[mi][hf] = l_st[mi][hf] * sc[mi][hf] + redl[row] + redl[128 + row];
            }
#pragma unroll
        for (int mi = 0; mi < 2; mi++)
#pragma unroll
            for (int ni = 0; ni < 4; ni++) {
                oacc[mi][ni][0] *= sc[mi][0]; oacc[mi][ni][1] *= sc[mi][0];
                oacc[mi][ni][2] *= sc[mi][1]; oacc[mi][ni][3] *= sc[mi][1];
            }
        // O += P * V   (V via ldmatrix.trans)
#pragma unroll
        for (int kk = 0; kk < 64; kk += 16) {
            unsigned a[2][4], bb[4][2];
#pragma unroll
            for (int mi = 0; mi < 2; mi++)
                ldm4(a[mi][0], a[mi][1], a[mi][2], a[mi][3],
                     sP + aqb + (unsigned)(mi*16*72*2 + kk*2));
#pragma unroll
            for (int j2 = 0; j2 < 2; j2++) {
                unsigned q0, q1, q2, q3;
                ldm4t(q0, q1, q2, q3, sVst + vtb + (unsigned)(kk*72*2 + j2*32));
                bb[2*j2][0] = q0; bb[2*j2][1] = q1;
                bb[2*j2+1][0] = q2; bb[2*j2+1][1] = q3;
            }
#pragma unroll
            for (int mi = 0; mi < 2; mi++)
#pragma unroll
                for (int ni = 0; ni < 4; ni++)
                    mma16(oacc[mi][ni], a[mi], bb[ni][0], bb[ni][1]);
        }
    }

    // epilogue: O = fp16(O / l)
#pragma unroll
    for (int mi = 0; mi < 2; mi++) {
        const int s0 = bm + wm*32 + mi*16 + grp;
        const float inv0 = 1.f / l_st[mi][0];
        const float inv1 = 1.f / l_st[mi][1];
#pragma unroll
        for (int ni = 0; ni < 4; ni++) {
            const int c = h*HDIM + wn*32 + ni*8 + qd*2;
            __half* o0 = O + ((size_t)s0     * BATCH + b) * DMODEL + c;
            __half* o1 = O + ((size_t)(s0+8) * BATCH + b) * DMODEL + c;
            *(unsigned*)o0 = pk2h(oacc[mi][ni][0]*inv0, oacc[mi][ni][1]*inv0);
            *(unsigned*)o1 = pk2h(oacc[mi][ni][2]*inv1, oacc[mi][ni][3]*inv1);
        }
    }
}

// ---------------------------------------------------------------------------
// out = LayerNorm(y + res) * g + b; optionally also writes fp16 copy.
// ---------------------------------------------------------------------------
template<bool DUAL>
__global__ void add_ln(const float* __restrict__ y, const float* __restrict__ res,
                       const float* __restrict__ g, const float* __restrict__ be,
                       float* __restrict__ out, __half* __restrict__ out_h)
{
    const int r   = blockIdx.x;
    const int tid = threadIdx.x;
    const float4 a  = ((const float4*)(y   + (size_t)r*DMODEL))[tid];
    const float4 b4 = ((const float4*)(res + (size_t)r*DMODEL))[tid];
    float x0 = a.x + b4.x, x1 = a.y + b4.y, x2 = a.z + b4.z, x3 = a.w + b4.w;
    float s = x0 + x1 + x2 + x3;
    float q = x0*x0 + x1*x1 + x2*x2 + x3*x3;

    __shared__ float rs[8], rq[8];
#pragma unroll
    for (int o = 16; o; o >>= 1) {
        s += __shfl_xor_sync(0xffffffffu, s, o);
        q += __shfl_xor_sync(0xffffffffu, q, o);
    }
    if ((tid & 31) == 0) { rs[tid >> 5] = s; rq[tid >> 5] = q; }
    __syncthreads();
    float st = 0.f, qt = 0.f;
#pragma unroll
    for (int i = 0; i < 8; i++) { st += rs[i]; qt += rq[i]; }
    const float mean = st * (1.f/1024.f);
    const float var  = qt * (1.f/1024.f) - mean*mean;
    const float rstd = rsqrtf(var + 1e-5f);

    const float4 gv = ((const float4*)g)[tid];
    const float4 bv = ((const float4*)be)[tid];
    float4 o;
    o.x = (x0 - mean) * rstd * gv.x + bv.x;
    o.y = (x1 - mean) * rstd * gv.y + bv.y;
    o.z = (x2 - mean) * rstd * gv.z + bv.z;
    o.w = (x3 - mean) * rstd * gv.w + bv.w;
    ((float4*)(out + (size_t)r*DMODEL))[tid] = o;
    if (DUAL) {
        uint2 u = make_uint2(pk2h(o.x, o.y), pk2h(o.z, o.w));
        ((uint2*)(out_h + (size_t)r*DMODEL))[tid] = u;
    }
}

// ---------------------------------------------------------------------------
extern "C" void kernel_launch(void* const* d_in, const int* in_sizes, int n_in,
                              void* d_out, int out_size)
{
    const float* state = (const float*)d_in[0];
    const void*  mask  = d_in[1];
    const float* Wq = (const float*)d_in[2];  const float* bq = (const float*)d_in[3];
    const float* Wk = (const float*)d_in[4];  const float* bk = (const float*)d_in[5];
    const float* Wv = (const float*)d_in[6];  const float* bv = (const float*)d_in[7];
    const float* Wo = (const float*)d_in[8];  const float* bo = (const float*)d_in[9];
    const float* g1 = (const float*)d_in[10]; const float* be1 = (const float*)d_in[11];
    const float* W1 = (const float*)d_in[12]; const float* b1 = (const float*)d_in[13];
    const float* W2 = (const float*)d_in[14]; const float* b2 = (const float*)d_in[15];
    const float* g2 = (const float*)d_in[16]; const float* be2 = (const float*)d_in[17];
    float* out = (float*)d_out;

    __half *state_h, *wq_h, *wk_h, *wv_h, *wo_h, *w1_h, *w2_h;
    __half *qh, *kh, *vh, *att_h, *x1_h, *hh;
    float *y, *x1, *y2;
    cudaGetSymbolAddress((void**)&state_h, g_state_h);
    cudaGetSymbolAddress((void**)&wq_h, g_wq_h);
    cudaGetSymbolAddress((void**)&wk_h, g_wk_h);
    cudaGetSymbolAddress((void**)&wv_h, g_wv_h);
    cudaGetSymbolAddress((void**)&wo_h, g_wo_h);
    cudaGetSymbolAddress((void**)&w1_h, g_w1_h);
    cudaGetSymbolAddress((void**)&w2_h, g_w2_h);
    cudaGetSymbolAddress((void**)&qh,  g_qh);
    cudaGetSymbolAddress((void**)&kh,  g_kh);
    cudaGetSymbolAddress((void**)&vh,  g_vh);
    cudaGetSymbolAddress((void**)&att_h, g_att_h);
    cudaGetSymbolAddress((void**)&x1_h, g_x1_h);
    cudaGetSymbolAddress((void**)&hh,  g_hh);
    cudaGetSymbolAddress((void**)&y,   g_y);
    cudaGetSymbolAddress((void**)&x1,  g_x1);
    cudaGetSymbolAddress((void**)&y2,  g_y2);

    cudaFuncSetAttribute(flash_attn_h, cudaFuncAttributeMaxDynamicSharedMemorySize,
                         FLASH_SMEM);
    cudaFuncSetAttribute(gemm_h<0>, cudaFuncAttributeMaxDynamicSharedMemorySize, G_SMEM);
    cudaFuncSetAttribute(gemm_h<1>, cudaFuncAttributeMaxDynamicSharedMemorySize, G_SMEM);
    cudaFuncSetAttribute(gemm_h<2>, cudaFuncAttributeMaxDynamicSharedMemorySize, G_SMEM);
    cudaFuncSetAttribute(gemm_qkv_h, cudaFuncAttributeMaxDynamicSharedMemorySize, G_SMEM);

    // single-launch converts (state + all 6 weights)
    f2h_all<<<dim3(4096, 1, 7), 256>>>(state, state_h, Wq, wq_h, Wk, wk_h,
                                       Wv, wv_h, Wo, wo_h, W1, w1_h, W2, w2_h);
    // fused QKV projection (fp16 out; q pre-scaled by 1/8)
    gemm_qkv_h<<<dim3(DMODEL/128, NROW/256, 3), 256, G_SMEM>>>(
        state_h, wq_h, wk_h, wv_h, bq, bk, bv, qh, kh, vh);
    // fused attention -> fp16 output
    flash_attn_h<<<dim3(SLEN/128, BATCH*NHEAD), 256, FLASH_SMEM>>>(qh, kh, vh, mask, att_h);
    // output projection + LN1 (dual write)
    gemm_h<0><<<dim3(DMODEL/128, NROW/256), 256, G_SMEM>>>(att_h, wo_h, bo, y, DMODEL, DMODEL);
    add_ln<true><<<NROW, 256>>>(y, state, g1, be1, x1, x1_h);
    // FFN (FF1 fp16+ReLU) + LN2
    gemm_h<2><<<dim3(FFDIM/128, NROW/256), 256, G_SMEM>>>(x1_h, w1_h, b1, hh, FFDIM, DMODEL);
    gemm_h<0><<<dim3(DMODEL/128, NROW/256), 256, G_SMEM>>>(hh, w2_h, b2, y2, DMODEL, FFDIM);
    add_ln<false><<<NROW, 256>>>(y2, x1, g2, be2, out, nullptr);
}

// round 14
// speedup vs baseline: 1.0186x; 1.0186x over previous
#include <cuda_runtime.h>
#include <cuda_fp16.h>
#include <math.h>
#include <stdint.h>

#define SLEN 2048
#define BATCH 4
#define DMODEL 1024
#define NHEAD 16
#define HDIM 64
#define FFDIM 4096
#define NROW (SLEN*BATCH)      /* 8192 */
#define LDAQ (BATCH*DMODEL)    /* 4096 */

// ------------------------- static scratch -----------------------------------
__device__ __half g_state_h[NROW*DMODEL];
__device__ __half g_wq_h[DMODEL*DMODEL];
__device__ __half g_wk_h[DMODEL*DMODEL];
__device__ __half g_wv_h[DMODEL*DMODEL];
__device__ __half g_wo_h[DMODEL*DMODEL];
__device__ __half g_w1_h[FFDIM*DMODEL];
__device__ __half g_w2_h[DMODEL*FFDIM];
__device__ __half g_qh [NROW*DMODEL];
__device__ __half g_kh [NROW*DMODEL];
__device__ __half g_vh [NROW*DMODEL];
__device__ __half g_att_h[NROW*DMODEL];
__device__ __half g_yh [NROW*DMODEL];
__device__ __half g_x1_h[NROW*DMODEL];
__device__ __half g_hh [NROW*FFDIM];
__device__ __half g_y2h[NROW*DMODEL];

// --------------------------- helpers ----------------------------------------
__device__ __forceinline__ unsigned pk2h(float x, float y) {
    __half2 h = __floats2half2_rn(x, y);
    return *(unsigned*)&h;
}
__device__ __forceinline__ void mma16(float* c, const unsigned* a, unsigned b0, unsigned b1) {
    asm("mma.sync.aligned.m16n8k16.row.col.f32.f16.f16.f32 "
        "{%0,%1,%2,%3},{%4,%5,%6,%7},{%8,%9},{%0,%1,%2,%3};"
        : "+f"(c[0]), "+f"(c[1]), "+f"(c[2]), "+f"(c[3])
        : "r"(a[0]), "r"(a[1]), "r"(a[2]), "r"(a[3]), "r"(b0), "r"(b1));
}
__device__ __forceinline__ void cp16(unsigned dst, const void* src) {
    asm volatile("cp.async.ca.shared.global [%0], [%1], 16;" :: "r"(dst), "l"(src));
}
__device__ __forceinline__ void ldm4(unsigned& r0, unsigned& r1, unsigned& r2, unsigned& r3,
                                     unsigned addr) {
    asm volatile("ldmatrix.sync.aligned.m8n8.x4.shared.b16 {%0,%1,%2,%3}, [%4];"
                 : "=r"(r0), "=r"(r1), "=r"(r2), "=r"(r3) : "r"(addr));
}
__device__ __forceinline__ void ldm4t(unsigned& r0, unsigned& r1, unsigned& r2, unsigned& r3,
                                      unsigned addr) {
    asm volatile("ldmatrix.sync.aligned.m8n8.x4.trans.shared.b16 {%0,%1,%2,%3}, [%4];"
                 : "=r"(r0), "=r"(r1), "=r"(r2), "=r"(r3) : "r"(addr));
}

// single-launch fp32 -> fp16 convert of all 7 tensors (grid.z selects segment)
__global__ void f2h_all(const float* s,  __half* so,
                        const float* w0, __half* o0, const float* w1, __half* o1,
                        const float* w2, __half* o2, const float* w3, __half* o3,
                        const float* w4, __half* o4, const float* w5, __half* o5)
{
    const int z = blockIdx.z;
    const float* in; __half* out; int n8;
    switch (z) {
        case 0: in = s;  out = so; n8 = NROW*DMODEL/8;   break;
        case 1: in = w0; out = o0; n8 = DMODEL*DMODEL/8; break;
        case 2: in = w1; out = o1; n8 = DMODEL*DMODEL/8; break;
        case 3: in = w2; out = o2; n8 = DMODEL*DMODEL/8; break;
        case 4: in = w3; out = o3; n8 = DMODEL*DMODEL/8; break;
        case 5: in = w4; out = o4; n8 = FFDIM*DMODEL/8;  break;
        default:in = w5; out = o5; n8 = DMODEL*FFDIM/8;  break;
    }
    int i = blockIdx.x * blockDim.x + threadIdx.x;
    if (i < n8) {
        const float4* p = (const float4*)in + 2*i;
        float4 a = p[0], b = p[1];
        uint4 o = make_uint4(pk2h(a.x,a.y), pk2h(a.z,a.w), pk2h(b.x,b.y), pk2h(b.z,b.w));
        ((uint4*)out)[i] = o;
    }
}

// ---------------------------------------------------------------------------
// fp16 dense GEMM:  C[M,N] = (A[M,K] * W[N,K]^T + bias) * oscale  (opt ReLU)
// 128x128xBK32 tiles, 4-stage cp.async (80KB dyn smem), m16n8k16, ldmatrix.
// OM: 1 = fp16 out, 2 = fp16 out + ReLU
// ---------------------------------------------------------------------------
#define GPITCH 40                       /* f16 per smem row */
#define GSLOTB (128*GPITCH*2)           /* bytes per stage per operand */
#define G_SMEM (4*GSLOTB*2)             /* 81920 */

template<int OM>
__device__ __forceinline__
void gemm_h_body(const __half* __restrict__ A, const __half* __restrict__ W,
                 const float* __restrict__ bias, void* __restrict__ Cout,
                 int N, int K, float oscale, void* gsm, int bm, int bn)
{
    const int tid = threadIdx.x;
    const int lane = tid & 31, wid = tid >> 5;
    const int wm = wid >> 2, wn = wid & 3;        // 2 x 4 warp grid, 64x32 tiles
    const int grp = lane >> 2, qd = lane & 3;
    const int row_in = lane & 7, mat = lane >> 3;
    const int r0 = tid >> 1, sg = (tid & 1) * 16;

    const unsigned sa = (unsigned)__cvta_generic_to_shared(gsm);
    const unsigned sb = sa + 4*GSLOTB;

    const __half* Ar = A + (size_t)(bm + r0) * K + sg;
    const __half* Wr = W + (size_t)(bn + r0) * K + sg;
    const unsigned dA = sa + (r0*GPITCH + sg)*2;
    const unsigned dB = sb + (r0*GPITCH + sg)*2;

    const unsigned a_base = (unsigned)(((wm*64 + (mat&1)*8 + row_in)*GPITCH + (mat>>1)*8)*2);
    const unsigned b_base = (unsigned)(((wn*32 + (mat>>1)*8 + row_in)*GPITCH + (mat&1)*8)*2);

    const int ktot = K >> 5;

    float acc[4][4][4];
#pragma unroll
    for (int i = 0; i < 4; i++)
#pragma unroll
        for (int j = 0; j < 4; j++)
#pragma unroll
            for (int x = 0; x < 4; x++) acc[i][j][x] = 0.f;

#pragma unroll
    for (int p = 0; p < 3; p++) {
        const unsigned off = p * GSLOTB;
        cp16(dA + off,      Ar + p*32);
        cp16(dA + off + 16, Ar + p*32 + 8);
        cp16(dB + off,      Wr + p*32);
        cp16(dB + off + 16, Wr + p*32 + 8);
        asm volatile("cp.async.commit_group;" ::: "memory");
    }

    for (int kt = 0; kt < ktot; kt++) {
        asm volatile("cp.async.wait_group 2;" ::: "memory");
        __syncthreads();
        const int nk = kt + 3;
        if (nk < ktot) {
            const unsigned off = (nk & 3) * GSLOTB;
            cp16(dA + off,      Ar + nk*32);
            cp16(dA + off + 16, Ar + nk*32 + 8);
            cp16(dB + off,      Wr + nk*32);
            cp16(dB + off + 16, Wr + nk*32 + 8);
        }
        asm volatile("cp.async.commit_group;" ::: "memory");

        const unsigned slA = sa + (kt & 3) * GSLOTB;
        const unsigned slB = sb + (kt & 3) * GSLOTB;
#pragma unroll
        for (int kk = 0; kk < 32; kk += 16) {
            unsigned a[4][4], b[4][2];
#pragma unroll
            for (int mi = 0; mi < 4; mi++)
                ldm4(a[mi][0], a[mi][1], a[mi][2], a[mi][3],
                     slA + a_base + (unsigned)(mi*16*GPITCH*2 + kk*2));
#pragma unroll
            for (int h2 = 0; h2 < 2; h2++) {
                unsigned q0, q1, q2, q3;
                ldm4(q0, q1, q2, q3,
                     slB + b_base + (unsigned)(h2*16*GPITCH*2 + kk*2));
                b[2*h2][0] = q0; b[2*h2][1] = q1;
                b[2*h2+1][0] = q2; b[2*h2+1][1] = q3;
            }
#pragma unroll
            for (int mi = 0; mi < 4; mi++)
#pragma unroll
                for (int ni = 0; ni < 4; ni++)
                    mma16(acc[mi][ni], a[mi], b[ni][0], b[ni][1]);
        }
    }

#pragma unroll
    for (int mi = 0; mi < 4; mi++) {
        const int row = bm + wm*64 + mi*16 + grp;
#pragma unroll
        for (int ni = 0; ni < 4; ni++) {
            const int col = bn + wn*32 + ni*8 + qd*2;
            float g0 = bias[col], g1 = bias[col+1];
            float o0 = (acc[mi][ni][0] + g0) * oscale;
            float o1 = (acc[mi][ni][1] + g1) * oscale;
            float o2 = (acc[mi][ni][2] + g0) * oscale;
            float o3 = (acc[mi][ni][3] + g1) * oscale;
            if (OM == 2) { o0=fmaxf(o0,0.f); o1=fmaxf(o1,0.f); o2=fmaxf(o2,0.f); o3=fmaxf(o3,0.f); }
            __half* Ch = (__half*)Cout;
            *(unsigned*)(Ch + (size_t)row    * N + col) = pk2h(o0, o1);
            *(unsigned*)(Ch + (size_t)(row+8)* N + col) = pk2h(o2, o3);
        }
    }
}

template<int OM>
__global__ __launch_bounds__(256, 2)
void gemm_h(const __half* __restrict__ A, const __half* __restrict__ W,
            const float* __restrict__ bias, void* __restrict__ Cout, int N, int K)
{
    extern __shared__ char gsm[];
    gemm_h_body<OM>(A, W, bias, Cout, N, K, 1.f, gsm, blockIdx.y*128, blockIdx.x*128);
}

// fused QKV: blockIdx.z selects weight/bias/output; q gets 0.125 scale
__global__ __launch_bounds__(256, 2)
void gemm_qkv_h(const __half* __restrict__ A,
                const __half* __restrict__ Wq, const __half* __restrict__ Wk,
                const __half* __restrict__ Wv,
                const float* __restrict__ bq, const float* __restrict__ bk,
                const float* __restrict__ bv,
                __half* __restrict__ Cq, __half* __restrict__ Ck, __half* __restrict__ Cv)
{
    extern __shared__ char gsm2[];
    const int z = blockIdx.z;
    const __half* W = (z == 0) ? Wq : (z == 1) ? Wk : Wv;
    const float* bias = (z == 0) ? bq : (z == 1) ? bk : bv;
    __half* C         = (z == 0) ? Cq : (z == 1) ? Ck : Cv;
    const float sc    = (z == 0) ? 0.125f : 1.f;
    gemm_h_body<1>(A, W, bias, C, DMODEL, DMODEL, sc, gsm2, blockIdx.y*128, blockIdx.x*128);
}

// ---------------------------------------------------------------------------
// Fused flash attention, fp16, m16n8k16, double-buffered K/V via cp.async.
// Q pre-scaled by 1/8 at QKV epilogue. Output fp16 [s*B+b, h*64+d].
// ---------------------------------------------------------------------------
#define KVSTAGE_B (64*72*2)     /* bytes per K (or V) stage */
#define FLASH_SMEM ((128*72 + 2*64*72 + 2*64*72 + 128*72)*2 + 256*4*2 + 2048)

__global__ __launch_bounds__(256, 2)
void flash_attn_h(const __half* __restrict__ Q, const __half* __restrict__ K,
                  const __half* __restrict__ V, const void* __restrict__ mask,
                  __half* __restrict__ O)
{
    extern __shared__ __half sm_h[];
    __half* Qs = sm_h;                  // 128*72
    __half* Ks = Qs + 128*72;           // 2 stages x 64*72
    __half* Vs = Ks + 2*64*72;          // 2 stages x 64*72
    __half* Ps = Vs + 2*64*72;          // 128*72
    float* redm = (float*)(Ps + 128*72);  // 256
    float* redl = redm + 256;             // 256
    unsigned char* msk = (unsigned char*)(redl + 256);  // 2048
    __shared__ int s_end;

    const int tid = threadIdx.x, lane = tid & 31, wid = tid >> 5;
    const int wm = wid >> 1, wn = wid & 1;       // 4 x 2 warps, 32x32 tiles
    const int grp = lane >> 2, qd = lane & 3;
    const int row_in = lane & 7, mat = lane >> 3;
    const int bh = blockIdx.y, b = bh >> 4, h = bh & 15;
    const int bm = blockIdx.x * 128;

    const __half* qb = Q + b*DMODEL + h*HDIM;
    const __half* kb = K + b*DMODEL + h*HDIM;
    const __half* vb = V + b*DMODEL + h*HDIM;

    const unsigned sQ = (unsigned)__cvta_generic_to_shared(Qs);
    const unsigned sK = (unsigned)__cvta_generic_to_shared(Ks);
    const unsigned sV = (unsigned)__cvta_generic_to_shared(Vs);
    const unsigned sP = (unsigned)__cvta_generic_to_shared(Ps);

    const unsigned aqb = (unsigned)(((wm*32 + (mat&1)*8 + row_in)*72 + (mat>>1)*8)*2);
    const unsigned bkb = (unsigned)(((wn*32 + (mat>>1)*8 + row_in)*72 + (mat&1)*8)*2);
    const unsigned vtb = (unsigned)((((mat&1)*8 + row_in)*72 + wn*32 + (mat>>1)*8)*2);

    const int rkv = tid >> 2, skv = (tid & 3) * 16;

    if (tid == 0) s_end = SLEN;
    // Q tile -> smem (group 1)
    {
        const int r = tid >> 1, sg = (tid & 1) * 32;
        const __half* src = qb + (size_t)(bm + r) * LDAQ + sg;
        const unsigned dst = sQ + (unsigned)((r*72 + sg)*2);
        cp16(dst,      src);
        cp16(dst + 16, src + 8);
        cp16(dst + 32, src + 16);
        cp16(dst + 48, src + 24);
        asm volatile("cp.async.commit_group;" ::: "memory");
    }
    // KV tile 0 -> stage 0 (group 2)
    {
        const __half* ks = kb + (size_t)rkv * LDAQ + skv;
        const __half* vs = vb + (size_t)rkv * LDAQ + skv;
        const unsigned dk = sK + (unsigned)((rkv*72 + skv)*2);
        const unsigned dv = sV + (unsigned)((rkv*72 + skv)*2);
        cp16(dk,      ks); cp16(dk + 16, ks + 8);
        cp16(dv,      vs); cp16(dv + 16, vs + 8);
        asm volatile("cp.async.commit_group;" ::: "memory");
    }
    // mask row -> smem (u8-bool or int32 probed at runtime)
    {
        const unsigned char* m8  = (const unsigned char*)mask;
        const int*           m32 = (const int*)mask;
        const bool isu8 = (m8[SLEN - 1] == 1);
        for (int t = tid; t < SLEN; t += 256)
            msk[t] = isu8 ? (m8[(size_t)b*SLEN + t] != 0)
                          : (m32[(size_t)b*SLEN + t] != 0);
    }
    asm volatile("cp.async.wait_group 0;" ::: "memory");
    __syncthreads();
    {
        int lm = SLEN;
        for (int t = tid; t < SLEN; t += 256)
            if (msk[t]) { lm = t; break; }
        if (lm < SLEN) atomicMin(&s_end, lm);
    }
    __syncthreads();
    const int kv_end = min(SLEN, (s_end + 63) & ~63);

    float m_st[2][2], l_st[2][2];
    float oacc[2][4][4];
#pragma unroll
    for (int mi = 0; mi < 2; mi++) {
        m_st[mi][0] = -INFINITY; m_st[mi][1] = -INFINITY;
        l_st[mi][0] = 0.f;       l_st[mi][1] = 0.f;
#pragma unroll
        for (int ni = 0; ni < 4; ni++)
#pragma unroll
            for (int x = 0; x < 4; x++) oacc[mi][ni][x] = 0.f;
    }

    for (int kt = 0; kt < kv_end; kt += 64) {
        const int st = (kt >> 6) & 1;
        __syncthreads();
        if (kt + 64 < kv_end) {
            const __half* ks = kb + (size_t)(kt + 64 + rkv) * LDAQ + skv;
            const __half* vs = vb + (size_t)(kt + 64 + rkv) * LDAQ + skv;
            const unsigned dk = sK + (unsigned)((st^1)*KVSTAGE_B) + (unsigned)((rkv*72 + skv)*2);
            const unsigned dv = sV + (unsigned)((st^1)*KVSTAGE_B) + (unsigned)((rkv*72 + skv)*2);
            cp16(dk,      ks); cp16(dk + 16, ks + 8);
            cp16(dv,      vs); cp16(dv + 16, vs + 8);
        }
        asm volatile("cp.async.commit_group;" ::: "memory");
        asm volatile("cp.async.wait_group 1;" ::: "memory");
        __syncthreads();

        const unsigned sKst = sK + (unsigned)(st*KVSTAGE_B);
        const unsigned sVst = sV + (unsigned)(st*KVSTAGE_B);

        // S = Q * K^T
        float sacc[2][4][4];
#pragma unroll
        for (int mi = 0; mi < 2; mi++)
#pragma unroll
            for (int ni = 0; ni < 4; ni++)
#pragma unroll
                for (int x = 0; x < 4; x++) sacc[mi][ni][x] = 0.f;
#pragma unroll
        for (int kk = 0; kk < 64; kk += 16) {
            unsigned a[2][4], bb[4][2];
#pragma unroll
            for (int mi = 0; mi < 2; mi++)
                ldm4(a[mi][0], a[mi][1], a[mi][2], a[mi][3],
                     sQ + aqb + (unsigned)(mi*16*72*2 + kk*2));
#pragma unroll
            for (int h2 = 0; h2 < 2; h2++) {
                unsigned q0, q1, q2, q3;
                ldm4(q0, q1, q2, q3, sKst + bkb + (unsigned)(h2*16*72*2 + kk*2));
                bb[2*h2][0] = q0; bb[2*h2][1] = q1;
                bb[2*h2+1][0] = q2; bb[2*h2+1][1] = q3;
            }
#pragma unroll
            for (int mi = 0; mi < 2; mi++)
#pragma unroll
                for (int ni = 0; ni < 4; ni++)
                    mma16(sacc[mi][ni], a[mi], bb[ni][0], bb[ni][1]);
        }
        // mask
#pragma unroll
        for (int ni = 0; ni < 4; ni++) {
            const int c0 = kt + wn*32 + ni*8 + qd*2;
            if (msk[c0]) {
                sacc[0][ni][0] = -INFINITY; sacc[0][ni][2] = -INFINITY;
                sacc[1][ni][0] = -INFINITY; sacc[1][ni][2] = -INFINITY;
            }
            if (msk[c0+1]) {
                sacc[0][ni][1] = -INFINITY; sacc[0][ni][3] = -INFINITY;
                sacc[1][ni][1] = -INFINITY; sacc[1][ni][3] = -INFINITY;
            }
        }
        // row max
#pragma unroll
        for (int mi = 0; mi < 2; mi++)
#pragma unroll
            for (int hf = 0; hf < 2; hf++) {
                float mx = -INFINITY;
#pragma unroll
                for (int ni = 0; ni < 4; ni++)
                    mx = fmaxf(mx, fmaxf(sacc[mi][ni][hf*2], sacc[mi][ni][hf*2+1]));
                mx = fmaxf(mx, __shfl_xor_sync(0xffffffffu, mx, 1));
                mx = fmaxf(mx, __shfl_xor_sync(0xffffffffu, mx, 2));
                if (qd == 0) redm[wn*128 + wm*32 + mi*16 + hf*8 + grp] = mx;
            }
        __syncthreads();

        float sc[2][2];
#pragma unroll
        for (int mi = 0; mi < 2; mi++)
#pragma unroll
            for (int hf = 0; hf < 2; hf++) {
                const int row = wm*32 + mi*16 + hf*8 + grp;
                const float tm = fmaxf(redm[row], redm[128 + row]);
                const float mnew = fmaxf(m_st[mi][hf], tm);
                sc[mi][hf] = __expf(m_st[mi][hf] - mnew);
                m_st[mi][hf] = mnew;
            }
        float ls[2][2] = {{0.f,0.f},{0.f,0.f}};
#pragma unroll
        for (int mi = 0; mi < 2; mi++) {
            const int r = wm*32 + mi*16 + grp;
#pragma unroll
            for (int ni = 0; ni < 4; ni++) {
                const int c = wn*32 + ni*8 + qd*2;
                float p0 = __expf(sacc[mi][ni][0] - m_st[mi][0]);
                float p1 = __expf(sacc[mi][ni][1] - m_st[mi][0]);
                float p2 = __expf(sacc[mi][ni][2] - m_st[mi][1]);
                float p3 = __expf(sacc[mi][ni][3] - m_st[mi][1]);
                ls[mi][0] += p0 + p1;
                ls[mi][1] += p2 + p3;
                *(unsigned*)(Ps + r*72 + c)     = pk2h(p0, p1);
                *(unsigned*)(Ps + (r+8)*72 + c) = pk2h(p2, p3);
            }
        }
#pragma unroll
        for (int mi = 0; mi < 2; mi++)
#pragma unroll
            for (int hf = 0; hf < 2; hf++) {
                float s = ls[mi][hf];
                s += __shfl_xor_sync(0xffffffffu, s, 1);
                s += __shfl_xor_sync(0xffffffffu, s, 2);
                if (qd == 0) redl[wn*128 + wm*32 + mi*16 + hf*8 + grp] = s;
            }
        __syncthreads();
#pragma unroll
        for (int mi = 0; mi < 2; mi++)
#pragma unroll
            for (int hf = 0; hf < 2; hf++) {
                const int row = wm*32 + mi*16 + hf*8 + grp;
                l_st[mi][hf] = l_st[mi][hf] * sc[mi][hf] + redl[row] + redl[128 + row];
            }
#pragma unroll
        for (int mi = 0; mi < 2; mi++)
#pragma unroll
            for (int ni = 0; ni < 4; ni++) {
                oacc[mi][ni][0] *= sc[mi][0]; oacc[mi][ni][1] *= sc[mi][0];
                oacc[mi][ni][2] *= sc[mi][1]; oacc[mi][ni][3] *= sc[mi][1];
            }
        // O += P * V   (V via ldmatrix.trans)
#pragma unroll
        for (int kk = 0; kk < 64; kk += 16) {
            unsigned a[2][4], bb[4][2];
#pragma unroll
            for (int mi = 0; mi < 2; mi++)
                ldm4(a[mi][0], a[mi][1], a[mi][2], a[mi][3],
                     sP + aqb + (unsigned)(mi*16*72*2 + kk*2));
#pragma unroll
            for (int j2 = 0; j2 < 2; j2++) {
                unsigned q0, q1, q2, q3;
                ldm4t(q0, q1, q2, q3, sVst + vtb + (unsigned)(kk*72*2 + j2*32));
                bb[2*j2][0] = q0; bb[2*j2][1] = q1;
                bb[2*j2+1][0] = q2; bb[2*j2+1][1] = q3;
            }
#pragma unroll
            for (int mi = 0; mi < 2; mi++)
#pragma unroll
                for (int ni = 0; ni < 4; ni++)
                    mma16(oacc[mi][ni], a[mi], bb[ni][0], bb[ni][1]);
        }
    }

    // epilogue: O = fp16(O / l)
#pragma unroll
    for (int mi = 0; mi < 2; mi++) {
        const int s0 = bm + wm*32 + mi*16 + grp;
        const float inv0 = 1.f / l_st[mi][0];
        const float inv1 = 1.f / l_st[mi][1];
#pragma unroll
        for (int ni = 0; ni < 4; ni++) {
            const int c = h*HDIM + wn*32 + ni*8 + qd*2;
            __half* o0 = O + ((size_t)s0     * BATCH + b) * DMODEL + c;
            __half* o1 = O + ((size_t)(s0+8) * BATCH + b) * DMODEL + c;
            *(unsigned*)o0 = pk2h(oacc[mi][ni][0]*inv0, oacc[mi][ni][1]*inv0);
            *(unsigned*)o1 = pk2h(oacc[mi][ni][2]*inv1, oacc[mi][ni][3]*inv1);
        }
    }
}

// ---------------------------------------------------------------------------
// LN1: x1_h = fp16( LayerNorm(y_h + res_f32) * g + b )
// ---------------------------------------------------------------------------
__global__ void add_ln1(const __half* __restrict__ y, const float* __restrict__ res,
                        const float* __restrict__ g, const float* __restrict__ be,
                        __half* __restrict__ out_h)
{
    const int r   = blockIdx.x;
    const int tid = threadIdx.x;
    const uint2 yv = ((const uint2*)(y + (size_t)r*DMODEL))[tid];
    const float2 h0 = __half22float2(*(const __half2*)&yv.x);
    const float2 h1 = __half22float2(*(const __half2*)&yv.y);
    const float4 b4 = ((const float4*)(res + (size_t)r*DMODEL))[tid];
    float x0 = h0.x + b4.x, x1 = h0.y + b4.y, x2 = h1.x + b4.z, x3 = h1.y + b4.w;
    float s = x0 + x1 + x2 + x3;
    float q = x0*x0 + x1*x1 + x2*x2 + x3*x3;

    __shared__ float rs[8], rq[8];
#pragma unroll
    for (int o = 16; o; o >>= 1) {
        s += __shfl_xor_sync(0xffffffffu, s, o);
        q += __shfl_xor_sync(0xffffffffu, q, o);
    }
    if ((tid & 31) == 0) { rs[tid >> 5] = s; rq[tid >> 5] = q; }
    __syncthreads();
    float st = 0.f, qt = 0.f;
#pragma unroll
    for (int i = 0; i < 8; i++) { st += rs[i]; qt += rq[i]; }
    const float mean = st * (1.f/1024.f);
    const float var  = qt * (1.f/1024.f) - mean*mean;
    const float rstd = rsqrtf(var + 1e-5f);

    const float4 gv = ((const float4*)g)[tid];
    const float4 bv = ((const float4*)be)[tid];
    float o0 = (x0 - mean) * rstd * gv.x + bv.x;
    float o1 = (x1 - mean) * rstd * gv.y + bv.y;
    float o2 = (x2 - mean) * rstd * gv.z + bv.z;
    float o3 = (x3 - mean) * rstd * gv.w + bv.w;
    uint2 u = make_uint2(pk2h(o0, o1), pk2h(o2, o3));
    ((uint2*)(out_h + (size_t)r*DMODEL))[tid] = u;
}

// ---------------------------------------------------------------------------
// LN2: out_f32 = LayerNorm(y2_h + res_h) * g + b   (final output)
// ---------------------------------------------------------------------------
__global__ void add_ln2(const __half* __restrict__ y, const __half* __restrict__ res,
                        const float* __restrict__ g, const float* __restrict__ be,
                        float* __restrict__ out)
{
    const int r   = blockIdx.x;
    const int tid = threadIdx.x;
    const uint2 yv = ((const uint2*)(y   + (size_t)r*DMODEL))[tid];
    const uint2 rv = ((const uint2*)(res + (size_t)r*DMODEL))[tid];
    const float2 h0 = __half22float2(*(const __half2*)&yv.x);
    const float2 h1 = __half22float2(*(const __half2*)&yv.y);
    const float2 r0 = __half22float2(*(const __half2*)&rv.x);
    const float2 r1 = __half22float2(*(const __half2*)&rv.y);
    float x0 = h0.x + r0.x, x1 = h0.y + r0.y, x2 = h1.x + r1.x, x3 = h1.y + r1.y;
    float s = x0 + x1 + x2 + x3;
    float q = x0*x0 + x1*x1 + x2*x2 + x3*x3;

    __shared__ float rs[8], rq[8];
#pragma unroll
    for (int o = 16; o; o >>= 1) {
        s += __shfl_xor_sync(0xffffffffu, s, o);
        q += __shfl_xor_sync(0xffffffffu, q, o);
    }
    if ((tid & 31) == 0) { rs[tid >> 5] = s; rq[tid >> 5] = q; }
    __syncthreads();
    float st = 0.f, qt = 0.f;
#pragma unroll
    for (int i = 0; i < 8; i++) { st += rs[i]; qt += rq[i]; }
    const float mean = st * (1.f/1024.f);
    const float var  = qt * (1.f/1024.f) - mean*mean;
    const float rstd = rsqrtf(var + 1e-5f);

    const float4 gv = ((const float4*)g)[tid];
    const float4 bv = ((const float4*)be)[tid];
    float4 o;
    o.x = (x0 - mean) * rstd * gv.x + bv.x;
    o.y = (x1 - mean) * rstd * gv.y + bv.y;
    o.z = (x2 - mean) * rstd * gv.z + bv.z;
    o.w = (x3 - mean) * rstd * gv.w + bv.w;
    ((float4*)(out + (size_t)r*DMODEL))[tid] = o;
}

// ---------------------------------------------------------------------------
extern "C" void kernel_launch(void* const* d_in, const int* in_sizes, int n_in,
                              void* d_out, int out_size)
{
    const float* state = (const float*)d_in[0];
    const void*  mask  = d_in[1];
    const float* Wq = (const float*)d_in[2];  const float* bq = (const float*)d_in[3];
    const float* Wk = (const float*)d_in[4];  const float* bk = (const float*)d_in[5];
    const float* Wv = (const float*)d_in[6];  const float* bv = (const float*)d_in[7];
    const float* Wo = (const float*)d_in[8];  const float* bo = (const float*)d_in[9];
    const float* g1 = (const float*)d_in[10]; const float* be1 = (const float*)d_in[11];
    const float* W1 = (const float*)d_in[12]; const float* b1 = (const float*)d_in[13];
    const float* W2 = (const float*)d_in[14]; const float* b2 = (const float*)d_in[15];
    const float* g2 = (const float*)d_in[16]; const float* be2 = (const float*)d_in[17];
    float* out = (float*)d_out;

    __half *state_h, *wq_h, *wk_h, *wv_h, *wo_h, *w1_h, *w2_h;
    __half *qh, *kh, *vh, *att_h, *yh, *x1_h, *hh, *y2h;
    cudaGetSymbolAddress((void**)&state_h, g_state_h);
    cudaGetSymbolAddress((void**)&wq_h, g_wq_h);
    cudaGetSymbolAddress((void**)&wk_h, g_wk_h);
    cudaGetSymbolAddress((void**)&wv_h, g_wv_h);
    cudaGetSymbolAddress((void**)&wo_h, g_wo_h);
    cudaGetSymbolAddress((void**)&w1_h, g_w1_h);
    cudaGetSymbolAddress((void**)&w2_h, g_w2_h);
    cudaGetSymbolAddress((void**)&qh,  g_qh);
    cudaGetSymbolAddress((void**)&kh,  g_kh);
    cudaGetSymbolAddress((void**)&vh,  g_vh);
    cudaGetSymbolAddress((void**)&att_h, g_att_h);
    cudaGetSymbolAddress((void**)&yh,  g_yh);
    cudaGetSymbolAddress((void**)&x1_h, g_x1_h);
    cudaGetSymbolAddress((void**)&hh,  g_hh);
    cudaGetSymbolAddress((void**)&y2h, g_y2h);

    cudaFuncSetAttribute(flash_attn_h, cudaFuncAttributeMaxDynamicSharedMemorySize,
                         FLASH_SMEM);
    cudaFuncSetAttribute(gemm_h<1>, cudaFuncAttributeMaxDynamicSharedMemorySize, G_SMEM);
    cudaFuncSetAttribute(gemm_h<2>, cudaFuncAttributeMaxDynamicSharedMemorySize, G_SMEM);
    cudaFuncSetAttribute(gemm_qkv_h, cudaFuncAttributeMaxDynamicSharedMemorySize, G_SMEM);

    // single-launch converts (state + all 6 weights)
    f2h_all<<<dim3(4096, 1, 7), 256>>>(state, state_h, Wq, wq_h, Wk, wk_h,
                                       Wv, wv_h, Wo, wo_h, W1, w1_h, W2, w2_h);
    // fused QKV projection (fp16 out; q pre-scaled by 1/8)
    gemm_qkv_h<<<dim3(DMODEL/128, NROW/128, 3), 256, G_SMEM>>>(
        state_h, wq_h, wk_h, wv_h, bq, bk, bv, qh, kh, vh);
    // fused attention -> fp16 output
    flash_attn_h<<<dim3(SLEN/128, BATCH*NHEAD), 256, FLASH_SMEM>>>(qh, kh, vh, mask, att_h);
    // output projection (fp16) + LN1 (fp16 out)
    gemm_h<1><<<dim3(DMODEL/128, NROW/128), 256, G_SMEM>>>(att_h, wo_h, bo, yh, DMODEL, DMODEL);
    add_ln1<<<NROW, 256>>>(yh, state, g1, be1, x1_h);
    // FFN (FF1 fp16+ReLU, FF2 fp16) + LN2 (fp32 final out)
    gemm_h<2><<<dim3(FFDIM/128, NROW/128), 256, G_SMEM>>>(x1_h, w1_h, b1, hh, FFDIM, DMODEL);
    gemm_h<1><<<dim3(DMODEL/128, NROW/128), 256, G_SMEM>>>(hh, w2_h, b2, y2h, DMODEL, FFDIM);
    add_ln2<<<NROW, 256>>>(y2h, x1_h, g2, be2, out);
}

// round 16
// speedup vs baseline: 1.0424x; 1.0234x over previous
#include <cuda_runtime.h>
#include <cuda_fp16.h>
#include <math.h>
#include <stdint.h>

#define SLEN 2048
#define BATCH 4
#define DMODEL 1024
#define NHEAD 16
#define HDIM 64
#define FFDIM 4096
#define NROW (SLEN*BATCH)      /* 8192 */
#define LDAQ (BATCH*DMODEL)    /* 4096 */

// ------------------------- static scratch -----------------------------------
__device__ __half g_state_h[NROW*DMODEL];
__device__ __half g_wq_h[DMODEL*DMODEL];
__device__ __half g_wk_h[DMODEL*DMODEL];
__device__ __half g_wv_h[DMODEL*DMODEL];
__device__ __half g_wo_h[DMODEL*DMODEL];
__device__ __half g_w1_h[FFDIM*DMODEL];
__device__ __half g_w2_h[DMODEL*FFDIM];
__device__ __half g_qh [NROW*DMODEL];
__device__ __half g_kh [NROW*DMODEL];
__device__ __half g_vh [NROW*DMODEL];
__device__ __half g_att_h[NROW*DMODEL];
__device__ __half g_yh [NROW*DMODEL];
__device__ __half g_x1_h[NROW*DMODEL];
__device__ __half g_hh [NROW*FFDIM];
__device__ __half g_y2h[NROW*DMODEL];

// --------------------------- helpers ----------------------------------------
__device__ __forceinline__ unsigned pk2h(float x, float y) {
    __half2 h = __floats2half2_rn(x, y);
    return *(unsigned*)&h;
}
__device__ __forceinline__ void mma16(float* c, const unsigned* a, unsigned b0, unsigned b1) {
    asm("mma.sync.aligned.m16n8k16.row.col.f32.f16.f16.f32 "
        "{%0,%1,%2,%3},{%4,%5,%6,%7},{%8,%9},{%0,%1,%2,%3};"
        : "+f"(c[0]), "+f"(c[1]), "+f"(c[2]), "+f"(c[3])
        : "r"(a[0]), "r"(a[1]), "r"(a[2]), "r"(a[3]), "r"(b0), "r"(b1));
}
__device__ __forceinline__ void cp16(unsigned dst, const void* src) {
    asm volatile("cp.async.ca.shared.global [%0], [%1], 16;" :: "r"(dst), "l"(src));
}
__device__ __forceinline__ void ldm4(unsigned& r0, unsigned& r1, unsigned& r2, unsigned& r3,
                                     unsigned addr) {
    asm volatile("ldmatrix.sync.aligned.m8n8.x4.shared.b16 {%0,%1,%2,%3}, [%4];"
                 : "=r"(r0), "=r"(r1), "=r"(r2), "=r"(r3) : "r"(addr));
}
__device__ __forceinline__ void ldm4t(unsigned& r0, unsigned& r1, unsigned& r2, unsigned& r3,
                                      unsigned addr) {
    asm volatile("ldmatrix.sync.aligned.m8n8.x4.trans.shared.b16 {%0,%1,%2,%3}, [%4];"
                 : "=r"(r0), "=r"(r1), "=r"(r2), "=r"(r3) : "r"(addr));
}

// single-launch fp32 -> fp16 convert of all 7 tensors (grid.z selects segment)
__global__ void f2h_all(const float* s,  __half* so,
                        const float* w0, __half* o0, const float* w1, __half* o1,
                        const float* w2, __half* o2, const float* w3, __half* o3,
                        const float* w4, __half* o4, const float* w5, __half* o5)
{
    const int z = blockIdx.z;
    const float* in; __half* out; int n8;
    switch (z) {
        case 0: in = s;  out = so; n8 = NROW*DMODEL/8;   break;
        case 1: in = w0; out = o0; n8 = DMODEL*DMODEL/8; break;
        case 2: in = w1; out = o1; n8 = DMODEL*DMODEL/8; break;
        case 3: in = w2; out = o2; n8 = DMODEL*DMODEL/8; break;
        case 4: in = w3; out = o3; n8 = DMODEL*DMODEL/8; break;
        case 5: in = w4; out = o4; n8 = FFDIM*DMODEL/8;  break;
        default:in = w5; out = o5; n8 = DMODEL*FFDIM/8;  break;
    }
    int i = blockIdx.x * blockDim.x + threadIdx.x;
    if (i < n8) {
        const float4* p = (const float4*)in + 2*i;
        float4 a = p[0], b = p[1];
        uint4 o = make_uint4(pk2h(a.x,a.y), pk2h(a.z,a.w), pk2h(b.x,b.y), pk2h(b.z,b.w));
        ((uint4*)out)[i] = o;
    }
}

// ---------------------------------------------------------------------------
// fp16 dense GEMM:  C[M,N] = (A[M,K] * W[N,K]^T + bias) * oscale  (opt ReLU)
// 128x128xBK32 tiles, 4-stage cp.async (80KB dyn smem), m16n8k16, ldmatrix.
// OM: 1 = fp16 out, 2 = fp16 out + ReLU
// ---------------------------------------------------------------------------
#define GPITCH 40                       /* f16 per smem row */
#define GSLOTB (128*GPITCH*2)           /* bytes per stage per operand */
#define G_SMEM (4*GSLOTB*2)             /* 81920 */

template<int OM>
__device__ __forceinline__
void gemm_h_body(const __half* __restrict__ A, const __half* __restrict__ W,
                 const float* __restrict__ bias, void* __restrict__ Cout,
                 int N, int K, float oscale, void* gsm, int bm, int bn)
{
    const int tid = threadIdx.x;
    const int lane = tid & 31, wid = tid >> 5;
    const int wm = wid >> 2, wn = wid & 3;        // 2 x 4 warp grid, 64x32 tiles
    const int grp = lane >> 2, qd = lane & 3;
    const int row_in = lane & 7, mat = lane >> 3;
    const int r0 = tid >> 1, sg = (tid & 1) * 16;

    const unsigned sa = (unsigned)__cvta_generic_to_shared(gsm);
    const unsigned sb = sa + 4*GSLOTB;

    const __half* Ar = A + (size_t)(bm + r0) * K + sg;
    const __half* Wr = W + (size_t)(bn + r0) * K + sg;
    const unsigned dA = sa + (r0*GPITCH + sg)*2;
    const unsigned dB = sb + (r0*GPITCH + sg)*2;

    const unsigned a_base = (unsigned)(((wm*64 + (mat&1)*8 + row_in)*GPITCH + (mat>>1)*8)*2);
    const unsigned b_base = (unsigned)(((wn*32 + (mat>>1)*8 + row_in)*GPITCH + (mat&1)*8)*2);

    const int ktot = K >> 5;

    float acc[4][4][4];
#pragma unroll
    for (int i = 0; i < 4; i++)
#pragma unroll
        for (int j = 0; j < 4; j++)
#pragma unroll
            for (int x = 0; x < 4; x++) acc[i][j][x] = 0.f;

#pragma unroll
    for (int p = 0; p < 3; p++) {
        const unsigned off = p * GSLOTB;
        cp16(dA + off,      Ar + p*32);
        cp16(dA + off + 16, Ar + p*32 + 8);
        cp16(dB + off,      Wr + p*32);
        cp16(dB + off + 16, Wr + p*32 + 8);
        asm volatile("cp.async.commit_group;" ::: "memory");
    }

    for (int kt = 0; kt < ktot; kt++) {
        asm volatile("cp.async.wait_group 2;" ::: "memory");
        __syncthreads();
        const int nk = kt + 3;
        if (nk < ktot) {
            const unsigned off = (nk & 3) * GSLOTB;
            cp16(dA + off,      Ar + nk*32);
            cp16(dA + off + 16, Ar + nk*32 + 8);
            cp16(dB + off,      Wr + nk*32);
            cp16(dB + off + 16, Wr + nk*32 + 8);
        }
        asm volatile("cp.async.commit_group;" ::: "memory");

        const unsigned slA = sa + (kt & 3) * GSLOTB;
        const unsigned slB = sb + (kt & 3) * GSLOTB;
#pragma unroll
        for (int kk = 0; kk < 32; kk += 16) {
            unsigned a[4][4], b[4][2];
#pragma unroll
            for (int mi = 0; mi < 4; mi++)
                ldm4(a[mi][0], a[mi][1], a[mi][2], a[mi][3],
                     slA + a_base + (unsigned)(mi*16*GPITCH*2 + kk*2));
#pragma unroll
            for (int h2 = 0; h2 < 2; h2++) {
                unsigned q0, q1, q2, q3;
                ldm4(q0, q1, q2, q3,
                     slB + b_base + (unsigned)(h2*16*GPITCH*2 + kk*2));
                b[2*h2][0] = q0; b[2*h2][1] = q1;
                b[2*h2+1][0] = q2; b[2*h2+1][1] = q3;
            }
#pragma unroll
            for (int mi = 0; mi < 4; mi++)
#pragma unroll
                for (int ni = 0; ni < 4; ni++)
                    mma16(acc[mi][ni], a[mi], b[ni][0], b[ni][1]);
        }
    }

#pragma unroll
    for (int mi = 0; mi < 4; mi++) {
        const int row = bm + wm*64 + mi*16 + grp;
#pragma unroll
        for (int ni = 0; ni < 4; ni++) {
            const int col = bn + wn*32 + ni*8 + qd*2;
            float g0 = bias[col], g1 = bias[col+1];
            float o0 = (acc[mi][ni][0] + g0) * oscale;
            float o1 = (acc[mi][ni][1] + g1) * oscale;
            float o2 = (acc[mi][ni][2] + g0) * oscale;
            float o3 = (acc[mi][ni][3] + g1) * oscale;
            if (OM == 2) { o0=fmaxf(o0,0.f); o1=fmaxf(o1,0.f); o2=fmaxf(o2,0.f); o3=fmaxf(o3,0.f); }
            __half* Ch = (__half*)Cout;
            *(unsigned*)(Ch + (size_t)row    * N + col) = pk2h(o0, o1);
            *(unsigned*)(Ch + (size_t)(row+8)* N + col) = pk2h(o2, o3);
        }
    }
}

template<int OM>
__global__ __launch_bounds__(256, 2)
void gemm_h(const __half* __restrict__ A, const __half* __restrict__ W,
            const float* __restrict__ bias, void* __restrict__ Cout, int N, int K)
{
    extern __shared__ char gsm[];
    gemm_h_body<OM>(A, W, bias, Cout, N, K, 1.f, gsm, blockIdx.y*128, blockIdx.x*128);
}

// fused QKV: blockIdx.z selects weight/bias/output; q gets 0.125 scale
__global__ __launch_bounds__(256, 2)
void gemm_qkv_h(const __half* __restrict__ A,
                const __half* __restrict__ Wq, const __half* __restrict__ Wk,
                const __half* __restrict__ Wv,
                const float* __restrict__ bq, const float* __restrict__ bk,
                const float* __restrict__ bv,
                __half* __restrict__ Cq, __half* __restrict__ Ck, __half* __restrict__ Cv)
{
    extern __shared__ char gsm2[];
    const int z = blockIdx.z;
    const __half* W = (z == 0) ? Wq : (z == 1) ? Wk : Wv;
    const float* bias = (z == 0) ? bq : (z == 1) ? bk : bv;
    __half* C         = (z == 0) ? Cq : (z == 1) ? Ck : Cv;
    const float sc    = (z == 0) ? 0.125f : 1.f;
    gemm_h_body<1>(A, W, bias, C, DMODEL, DMODEL, sc, gsm2, blockIdx.y*128, blockIdx.x*128);
}

// ---------------------------------------------------------------------------
// Fused flash attention, FA2 warp layout: 8 warps x (16 q-rows, all 64 keys).
// S stays in registers (repacked as PV A-frags); softmax reductions are
// qd-lane shuffles; 2 barriers per KV tile. fp16, double-buffered K/V.
// ---------------------------------------------------------------------------
#define KVSTAGE_B (64*72*2)     /* bytes per K (or V) stage */
#define FLASH_SMEM ((128*72 + 2*64*72 + 2*64*72)*2 + 2048 + 16)

__global__ __launch_bounds__(256, 2)
void flash_attn_h(const __half* __restrict__ Q, const __half* __restrict__ K,
                  const __half* __restrict__ V, const void* __restrict__ mask,
                  __half* __restrict__ O)
{
    extern __shared__ __half sm_h[];
    __half* Qs = sm_h;                  // 128*72
    __half* Ks = Qs + 128*72;           // 2 stages x 64*72
    __half* Vs = Ks + 2*64*72;          // 2 stages x 64*72
    unsigned char* msk = (unsigned char*)(Vs + 2*64*72);  // 2048
    __shared__ int s_end;

    const int tid = threadIdx.x, lane = tid & 31, wid = tid >> 5;
    const int grp = lane >> 2, qd = lane & 3;
    const int row_in = lane & 7, mat = lane >> 3;
    const int bh = blockIdx.y, b = bh >> 4, h = bh & 15;
    const int bm = blockIdx.x * 128;

    const __half* qb = Q + b*DMODEL + h*HDIM;
    const __half* kb = K + b*DMODEL + h*HDIM;
    const __half* vb = V + b*DMODEL + h*HDIM;

    const unsigned sQ = (unsigned)__cvta_generic_to_shared(Qs);
    const unsigned sK = (unsigned)__cvta_generic_to_shared(Ks);
    const unsigned sV = (unsigned)__cvta_generic_to_shared(Vs);

    const unsigned aqb = (unsigned)(((wid*16 + (mat&1)*8 + row_in)*72 + (mat>>1)*8)*2);
    const unsigned bkb = (unsigned)((((mat>>1)*8 + row_in)*72 + (mat&1)*8)*2);
    const unsigned vtb = (unsigned)((((mat&1)*8 + row_in)*72 + (mat>>1)*8)*2);

    const int rkv = tid >> 2, skv = (tid & 3) * 16;

    if (tid == 0) s_end = SLEN;
    // Q tile -> smem (group 1)
    {
        const int r = tid >> 1, sg = (tid & 1) * 32;
        const __half* src = qb + (size_t)(bm + r) * LDAQ + sg;
        const unsigned dst = sQ + (unsigned)((r*72 + sg)*2);
        cp16(dst,      src);
        cp16(dst + 16, src + 8);
        cp16(dst + 32, src + 16);
        cp16(dst + 48, src + 24);
        asm volatile("cp.async.commit_group;" ::: "memory");
    }
    // KV tile 0 -> stage 0 (group 2)
    {
        const __half* ks = kb + (size_t)rkv * LDAQ + skv;
        const __half* vs = vb + (size_t)rkv * LDAQ + skv;
        const unsigned dk = sK + (unsigned)((rkv*72 + skv)*2);
        const unsigned dv = sV + (unsigned)((rkv*72 + skv)*2);
        cp16(dk,      ks); cp16(dk + 16, ks + 8);
        cp16(dv,      vs); cp16(dv + 16, vs + 8);
        asm volatile("cp.async.commit_group;" ::: "memory");
    }
    // mask row -> smem (u8-bool or int32 probed at runtime)
    {
        const unsigned char* m8  = (const unsigned char*)mask;
        const int*           m32 = (const int*)mask;
        const bool isu8 = (m8[SLEN - 1] == 1);
        for (int t = tid; t < SLEN; t += 256)
            msk[t] = isu8 ? (m8[(size_t)b*SLEN + t] != 0)
                          : (m32[(size_t)b*SLEN + t] != 0);
    }
    asm volatile("cp.async.wait_group 0;" ::: "memory");
    __syncthreads();
    {
        int lm = SLEN;
        for (int t = tid; t < SLEN; t += 256)
            if (msk[t]) { lm = t; break; }
        if (lm < SLEN) atomicMin(&s_end, lm);
    }
    __syncthreads();
    const int kv_end = min(SLEN, (s_end + 63) & ~63);

    float m_st[2] = {-INFINITY, -INFINITY};
    float l_st[2] = {0.f, 0.f};
    float oacc[8][4];
#pragma unroll
    for (int ni = 0; ni < 8; ni++)
#pragma unroll
        for (int x = 0; x < 4; x++) oacc[ni][x] = 0.f;

    for (int kt = 0; kt < kv_end; kt += 64) {
        const int st = (kt >> 6) & 1;
        __syncthreads();
        if (kt + 64 < kv_end) {
            const __half* ks = kb + (size_t)(kt + 64 + rkv) * LDAQ + skv;
            const __half* vs = vb + (size_t)(kt + 64 + rkv) * LDAQ + skv;
            const unsigned dk = sK + (unsigned)((st^1)*KVSTAGE_B) + (unsigned)((rkv*72 + skv)*2);
            const unsigned dv = sV + (unsigned)((st^1)*KVSTAGE_B) + (unsigned)((rkv*72 + skv)*2);
            cp16(dk,      ks); cp16(dk + 16, ks + 8);
            cp16(dv,      vs); cp16(dv + 16, vs + 8);
        }
        asm volatile("cp.async.commit_group;" ::: "memory");
        asm volatile("cp.async.wait_group 1;" ::: "memory");
        __syncthreads();

        const unsigned sKst = sK + (unsigned)(st*KVSTAGE_B);
        const unsigned sVst = sV + (unsigned)(st*KVSTAGE_B);

        // S = Q * K^T : warp computes 16 x 64
        float sacc[8][4];
#pragma unroll
        for (int ni = 0; ni < 8; ni++)
#pragma unroll
            for (int x = 0; x < 4; x++) sacc[ni][x] = 0.f;
#pragma unroll
        for (int kk = 0; kk < 64; kk += 16) {
            unsigned a[4], bb[8][2];
            ldm4(a[0], a[1], a[2], a[3], sQ + aqb + (unsigned)(kk*2));
#pragma unroll
            for (int g = 0; g < 4; g++) {
                unsigned q0, q1, q2, q3;
                ldm4(q0, q1, q2, q3, sKst + bkb + (unsigned)(g*16*72*2 + kk*2));
                bb[2*g][0] = q0; bb[2*g][1] = q1;
                bb[2*g+1][0] = q2; bb[2*g+1][1] = q3;
            }
#pragma unroll
            for (int ni = 0; ni < 8; ni++)
                mma16(sacc[ni], a, bb[ni][0], bb[ni][1]);
        }
        // mask
#pragma unroll
        for (int ni = 0; ni < 8; ni++) {
            const int c0 = kt + ni*8 + qd*2;
            if (msk[c0])   { sacc[ni][0] = -INFINITY; sacc[ni][2] = -INFINITY; }
            if (msk[c0+1]) { sacc[ni][1] = -INFINITY; sacc[ni][3] = -INFINITY; }
        }
        // row max: intra-thread over ni, then qd-lane shuffles
        float sc0, sc1;
        {
            float mx0 = -INFINITY, mx1 = -INFINITY;
#pragma unroll
            for (int ni = 0; ni < 8; ni++) {
                mx0 = fmaxf(mx0, fmaxf(sacc[ni][0], sacc[ni][1]));
                mx1 = fmaxf(mx1, fmaxf(sacc[ni][2], sacc[ni][3]));
            }
            mx0 = fmaxf(mx0, __shfl_xor_sync(0xffffffffu, mx0, 1));
            mx0 = fmaxf(mx0, __shfl_xor_sync(0xffffffffu, mx0, 2));
            mx1 = fmaxf(mx1, __shfl_xor_sync(0xffffffffu, mx1, 1));
            mx1 = fmaxf(mx1, __shfl_xor_sync(0xffffffffu, mx1, 2));
            const float m0 = fmaxf(m_st[0], mx0);
            const float m1 = fmaxf(m_st[1], mx1);
            sc0 = __expf(m_st[0] - m0);
            sc1 = __expf(m_st[1] - m1);
            m_st[0] = m0; m_st[1] = m1;
        }
        // exp + sums + pack P into PV a-frag registers
        unsigned ph0[8], ph1[8];
        {
            float ls0 = 0.f, ls1 = 0.f;
#pragma unroll
            for (int ni = 0; ni < 8; ni++) {
                float p0 = __expf(sacc[ni][0] - m_st[0]);
                float p1 = __expf(sacc[ni][1] - m_st[0]);
                float p2 = __expf(sacc[ni][2] - m_st[1]);
                float p3 = __expf(sacc[ni][3] - m_st[1]);
                ls0 += p0 + p1;
                ls1 += p2 + p3;
                ph0[ni] = pk2h(p0, p1);
                ph1[ni] = pk2h(p2, p3);
            }
            ls0 += __shfl_xor_sync(0xffffffffu, ls0, 1);
            ls0 += __shfl_xor_sync(0xffffffffu, ls0, 2);
            ls1 += __shfl_xor_sync(0xffffffffu, ls1, 1);
            ls1 += __shfl_xor_sync(0xffffffffu, ls1, 2);
            l_st[0] = l_st[0] * sc0 + ls0;
            l_st[1] = l_st[1] * sc1 + ls1;
        }
        // rescale O
#pragma unroll
        for (int ni = 0; ni < 8; ni++) {
            oacc[ni][0] *= sc0; oacc[ni][1] *= sc0;
            oacc[ni][2] *= sc1; oacc[ni][3] *= sc1;
        }
        // O += P * V   (A from registers, V via ldmatrix.trans)
#pragma unroll
        for (int j = 0; j < 4; j++) {
            unsigned a[4];
            a[0] = ph0[2*j];   a[1] = ph1[2*j];
            a[2] = ph0[2*j+1]; a[3] = ph1[2*j+1];
            unsigned bb[8][2];
#pragma unroll
            for (int g = 0; g < 4; g++) {
                unsigned q0, q1, q2, q3;
                ldm4t(q0, q1, q2, q3,
                      sVst + vtb + (unsigned)(j*16*72*2 + g*16*2));
                bb[2*g][0] = q0; bb[2*g][1] = q1;
                bb[2*g+1][0] = q2; bb[2*g+1][1] = q3;
            }
#pragma unroll
            for (int ni = 0; ni < 8; ni++)
                mma16(oacc[ni], a, bb[ni][0], bb[ni][1]);
        }
    }

    // epilogue: O = fp16(O / l), rows bm + wid*16 + grp (+8)
    {
        const int s0 = bm + wid*16 + grp;
        const float inv0 = 1.f / l_st[0];
        const float inv1 = 1.f / l_st[1];
#pragma unroll
        for (int ni = 0; ni < 8; ni++) {
            const int c = h*HDIM + ni*8 + qd*2;
            __half* o0 = O + ((size_t)s0     * BATCH + b) * DMODEL + c;
            __half* o1 = O + ((size_t)(s0+8) * BATCH + b) * DMODEL + c;
            *(unsigned*)o0 = pk2h(oacc[ni][0]*inv0, oacc[ni][1]*inv0);
            *(unsigned*)o1 = pk2h(oacc[ni][2]*inv1, oacc[ni][3]*inv1);
        }
    }
}

// ---------------------------------------------------------------------------
// LN1: x1_h = fp16( LayerNorm(y_h + res_f32) * g + b )
// ---------------------------------------------------------------------------
__global__ void add_ln1(const __half* __restrict__ y, const float* __restrict__ res,
                        const float* __restrict__ g, const float* __restrict__ be,
                        __half* __restrict__ out_h)
{
    const int r   = blockIdx.x;
    const int tid = threadIdx.x;
    const uint2 yv = ((const uint2*)(y + (size_t)r*DMODEL))[tid];
    const float2 h0 = __half22float2(*(const __half2*)&yv.x);
    const float2 h1 = __half22float2(*(const __half2*)&yv.y);
    const float4 b4 = ((const float4*)(res + (size_t)r*DMODEL))[tid];
    float x0 = h0.x + b4.x, x1 = h0.y + b4.y, x2 = h1.x + b4.z, x3 = h1.y + b4.w;
    float s = x0 + x1 + x2 + x3;
    float q = x0*x0 + x1*x1 + x2*x2 + x3*x3;

    __shared__ float rs[8], rq[8];
#pragma unroll
    for (int o = 16; o; o >>= 1) {
        s += __shfl_xor_sync(0xffffffffu, s, o);
        q += __shfl_xor_sync(0xffffffffu, q, o);
    }
    if ((tid & 31) == 0) { rs[tid >> 5] = s; rq[tid >> 5] = q; }
    __syncthreads();
    float st = 0.f, qt = 0.f;
#pragma unroll
    for (int i = 0; i < 8; i++) { st += rs[i]; qt += rq[i]; }
    const float mean = st * (1.f/1024.f);
    const float var  = qt * (1.f/1024.f) - mean*mean;
    const float rstd = rsqrtf(var + 1e-5f);

    const float4 gv = ((const float4*)g)[tid];
    const float4 bv = ((const float4*)be)[tid];
    float o0 = (x0 - mean) * rstd * gv.x + bv.x;
    float o1 = (x1 - mean) * rstd * gv.y + bv.y;
    float o2 = (x2 - mean) * rstd * gv.z + bv.z;
    float o3 = (x3 - mean) * rstd * gv.w + bv.w;
    uint2 u = make_uint2(pk2h(o0, o1), pk2h(o2, o3));
    ((uint2*)(out_h + (size_t)r*DMODEL))[tid] = u;
}

// ---------------------------------------------------------------------------
// LN2: out_f32 = LayerNorm(y2_h + res_h) * g + b   (final output)
// ---------------------------------------------------------------------------
__global__ void add_ln2(const __half* __restrict__ y, const __half* __restrict__ res,
                        const float* __restrict__ g, const float* __restrict__ be,
                        float* __restrict__ out)
{
    const int r   = blockIdx.x;
    const int tid = threadIdx.x;
    const uint2 yv = ((const uint2*)(y   + (size_t)r*DMODEL))[tid];
    const uint2 rv = ((const uint2*)(res + (size_t)r*DMODEL))[tid];
    const float2 h0 = __half22float2(*(const __half2*)&yv.x);
    const float2 h1 = __half22float2(*(const __half2*)&yv.y);
    const float2 r0 = __half22float2(*(const __half2*)&rv.x);
    const float2 r1 = __half22float2(*(const __half2*)&rv.y);
    float x0 = h0.x + r0.x, x1 = h0.y + r0.y, x2 = h1.x + r1.x, x3 = h1.y + r1.y;
    float s = x0 + x1 + x2 + x3;
    float q = x0*x0 + x1*x1 + x2*x2 + x3*x3;

    __shared__ float rs[8], rq[8];
#pragma unroll
    for (int o = 16; o; o >>= 1) {
        s += __shfl_xor_sync(0xffffffffu, s, o);
        q += __shfl_xor_sync(0xffffffffu, q, o);
    }
    if ((tid & 31) == 0) { rs[tid >> 5] = s; rq[tid >> 5] = q; }
    __syncthreads();
    float st = 0.f, qt = 0.f;
#pragma unroll
    for (int i = 0; i < 8; i++) { st += rs[i]; qt += rq[i]; }
    const float mean = st * (1.f/1024.f);
    const float var  = qt * (1.f/1024.f) - mean*mean;
    const float rstd = rsqrtf(var + 1e-5f);

    const float4 gv = ((const float4*)g)[tid];
    const float4 bv = ((const float4*)be)[tid];
    float4 o;
    o.x = (x0 - mean) * rstd * gv.x + bv.x;
    o.y = (x1 - mean) * rstd * gv.y + bv.y;
    o.z = (x2 - mean) * rstd * gv.z + bv.z;
    o.w = (x3 - mean) * rstd * gv.w + bv.w;
    ((float4*)(out + (size_t)r*DMODEL))[tid] = o;
}

// ---------------------------------------------------------------------------
extern "C" void kernel_launch(void* const* d_in, const int* in_sizes, int n_in,
                              void* d_out, int out_size)
{
    const float* state = (const float*)d_in[0];
    const void*  mask  = d_in[1];
    const float* Wq = (const float*)d_in[2];  const float* bq = (const float*)d_in[3];
    const float* Wk = (const float*)d_in[4];  const float* bk = (const float*)d_in[5];
    const float* Wv = (const float*)d_in[6];  const float* bv = (const float*)d_in[7];
    const float* Wo = (const float*)d_in[8];  const float* bo = (const float*)d_in[9];
    const float* g1 = (const float*)d_in[10]; const float* be1 = (const float*)d_in[11];
    const float* W1 = (const float*)d_in[12]; const float* b1 = (const float*)d_in[13];
    const float* W2 = (const float*)d_in[14]; const float* b2 = (const float*)d_in[15];
    const float* g2 = (const float*)d_in[16]; const float* be2 = (const float*)d_in[17];
    float* out = (float*)d_out;

    __half *state_h, *wq_h, *wk_h, *wv_h, *wo_h, *w1_h, *w2_h;
    __half *qh, *kh, *vh, *att_h, *yh, *x1_h, *hh, *y2h;
    cudaGetSymbolAddress((void**)&state_h, g_state_h);
    cudaGetSymbolAddress((void**)&wq_h, g_wq_h);
    cudaGetSymbolAddress((void**)&wk_h, g_wk_h);
    cudaGetSymbolAddress((void**)&wv_h, g_wv_h);
    cudaGetSymbolAddress((void**)&wo_h, g_wo_h);
    cudaGetSymbolAddress((void**)&w1_h, g_w1_h);
    cudaGetSymbolAddress((void**)&w2_h, g_w2_h);
    cudaGetSymbolAddress((void**)&qh,  g_qh);
    cudaGetSymbolAddress((void**)&kh,  g_kh);
    cudaGetSymbolAddress((void**)&vh,  g_vh);
    cudaGetSymbolAddress((void**)&att_h, g_att_h);
    cudaGetSymbolAddress((void**)&yh,  g_yh);
    cudaGetSymbolAddress((void**)&x1_h, g_x1_h);
    cudaGetSymbolAddress((void**)&hh,  g_hh);
    cudaGetSymbolAddress((void**)&y2h, g_y2h);

    cudaFuncSetAttribute(flash_attn_h, cudaFuncAttributeMaxDynamicSharedMemorySize,
                         FLASH_SMEM);
    cudaFuncSetAttribute(gemm_h<1>, cudaFuncAttributeMaxDynamicSharedMemorySize, G_SMEM);
    cudaFuncSetAttribute(gemm_h<2>, cudaFuncAttributeMaxDynamicSharedMemorySize, G_SMEM);
    cudaFuncSetAttribute(gemm_qkv_h, cudaFuncAttributeMaxDynamicSharedMemorySize, G_SMEM);

    // single-launch converts (state + all 6 weights)
    f2h_all<<<dim3(4096, 1, 7), 256>>>(state, state_h, Wq, wq_h, Wk, wk_h,
                                       Wv, wv_h, Wo, wo_h, W1, w1_h, W2, w2_h);
    // fused QKV projection (fp16 out; q pre-scaled by 1/8)
    gemm_qkv_h<<<dim3(DMODEL/128, NROW/128, 3), 256, G_SMEM>>>(
        state_h, wq_h, wk_h, wv_h, bq, bk, bv, qh, kh, vh);
    // fused attention -> fp16 output
    flash_attn_h<<<dim3(SLEN/128, BATCH*NHEAD), 256, FLASH_SMEM>>>(qh, kh, vh, mask, att_h);
    // output projection (fp16) + LN1 (fp16 out)
    gemm_h<1><<<dim3(DMODEL/128, NROW/128), 256, G_SMEM>>>(att_h, wo_h, bo, yh, DMODEL, DMODEL);
    add_ln1<<<NROW, 256>>>(yh, state, g1, be1, x1_h);
    // FFN (FF1 fp16+ReLU, FF2 fp16) + LN2 (fp32 final out)
    gemm_h<2><<<dim3(FFDIM/128, NROW/128), 256, G_SMEM>>>(x1_h, w1_h, b1, hh, FFDIM, DMODEL);
    gemm_h<1><<<dim3(DMODEL/128, NROW/128), 256, G_SMEM>>>(hh, w2_h, b2, y2h, DMODEL, FFDIM);
    add_ln2<<<NROW, 256>>>(y2h, x1_h, g2, be2, out);
}